// round 1
// baseline (speedup 1.0000x reference)
#include <cuda_runtime.h>
#include <cuda_bf16.h>
#include <cstdint>

#define BB 8
#define HH 8
#define NN 16384
#define KSLOT 64
#define DQ 256
#define DH 64
#define DMLP 512
#define NSPLIT 8

// ---------------- scratch (static device globals; no allocation allowed) ----
__device__ __nv_bfloat16 g_hits[(size_t)BB * NN * DQ];          // 67 MB
__device__ __nv_bfloat16 g_Wkvt[1024 * 256];                    // [out col][in k], bf16
__device__ __nv_bfloat16 g_q[(size_t)BB * HH * 64 * 64];        // [b][h][k][d], *0.125
__device__ __nv_bfloat16 g_kv[(size_t)BB * NN * 1024];          // 256 MB [b*N+n][k heads|v heads]
__device__ float g_pm[BB * HH * NSPLIT * 64];
__device__ float g_pl[BB * HH * NSPLIT * 64];
__device__ float g_po[(size_t)BB * HH * NSPLIT * 64 * 64];
__device__ float g_attv[(size_t)BB * KSLOT * 512];

// ---------------- small PTX helpers ----------------------------------------
__device__ __forceinline__ uint32_t smaddr(const void* p) {
    return (uint32_t)__cvta_generic_to_shared(p);
}
__device__ __forceinline__ void ldsm4(uint32_t& r0, uint32_t& r1, uint32_t& r2, uint32_t& r3,
                                      const void* p) {
    uint32_t a = smaddr(p);
    asm volatile("ldmatrix.sync.aligned.m8n8.x4.shared.b16 {%0,%1,%2,%3},[%4];"
                 : "=r"(r0), "=r"(r1), "=r"(r2), "=r"(r3) : "r"(a));
}
__device__ __forceinline__ void ldsm4t(uint32_t& r0, uint32_t& r1, uint32_t& r2, uint32_t& r3,
                                       const void* p) {
    uint32_t a = smaddr(p);
    asm volatile("ldmatrix.sync.aligned.m8n8.x4.trans.shared.b16 {%0,%1,%2,%3},[%4];"
                 : "=r"(r0), "=r"(r1), "=r"(r2), "=r"(r3) : "r"(a));
}
__device__ __forceinline__ void mma16816(float* c, const uint32_t* a, uint32_t b0, uint32_t b1) {
    asm volatile("mma.sync.aligned.m16n8k16.row.col.f32.bf16.bf16.f32 "
                 "{%0,%1,%2,%3},{%4,%5,%6,%7},{%8,%9},{%0,%1,%2,%3};"
                 : "+f"(c[0]), "+f"(c[1]), "+f"(c[2]), "+f"(c[3])
                 : "r"(a[0]), "r"(a[1]), "r"(a[2]), "r"(a[3]), "r"(b0), "r"(b1));
}
__device__ __forceinline__ void cpasync16(void* dst, const void* src) {
    uint32_t d = smaddr(dst);
    asm volatile("cp.async.ca.shared.global [%0],[%1],16;" :: "r"(d), "l"(src) : "memory");
}
__device__ __forceinline__ uint32_t packbf(float a, float b) {
    __nv_bfloat162 t = __floats2bfloat162_rn(a, b);
    return *reinterpret_cast<uint32_t*>(&t);
}

// ---------------- K0a: hits fp32 -> bf16 ------------------------------------
__global__ void cvt_hits(const float4* __restrict__ in, int nvec) {
    __nv_bfloat162* out = reinterpret_cast<__nv_bfloat162*>(g_hits);
    for (int i = blockIdx.x * blockDim.x + threadIdx.x; i < nvec; i += gridDim.x * blockDim.x) {
        float4 v = in[i];
        out[2 * i]     = __floats2bfloat162_rn(v.x, v.y);
        out[2 * i + 1] = __floats2bfloat162_rn(v.z, v.w);
    }
}

// ---------------- K0b: [Wk|Wv] transposed -> bf16 ---------------------------
__global__ void prep_w(const float* __restrict__ Wk, const float* __restrict__ Wv) {
    int i = blockIdx.x * blockDim.x + threadIdx.x;     // 0..262143
    int j = i >> 8, kk = i & 255;                      // j: out col 0..1023
    float v = (j < 512) ? Wk[kk * 512 + j] : Wv[kk * 512 + (j - 512)];
    g_Wkvt[i] = __float2bfloat16(v);
}

// ---------------- K1: LN1 + Q projection ------------------------------------
__global__ void __launch_bounds__(256) ln1_q(const float* __restrict__ slots,
                                             const float* __restrict__ g1,
                                             const float* __restrict__ be1,
                                             const float* __restrict__ Wq) {
    __shared__ float xs[256];
    __shared__ float red[256];
    int row = blockIdx.x, t = threadIdx.x;
    int b = row >> 6, k = row & 63;
    float x = slots[(size_t)row * 256 + t];
    red[t] = x; __syncthreads();
    for (int off = 128; off; off >>= 1) { if (t < off) red[t] += red[t + off]; __syncthreads(); }
    float mean = red[0] * (1.f / 256.f);
    __syncthreads();
    float d = x - mean;
    red[t] = d * d; __syncthreads();
    for (int off = 128; off; off >>= 1) { if (t < off) red[t] += red[t + off]; __syncthreads(); }
    float var = red[0] * (1.f / 256.f);
    float xn = d * rsqrtf(var + 1e-5f) * g1[t] + be1[t];
    __syncthreads();
    xs[t] = xn;
    __syncthreads();
#pragma unroll
    for (int jj = 0; jj < 2; jj++) {
        int j = t + jj * 256;
        float acc = 0.f;
#pragma unroll 8
        for (int kk = 0; kk < 256; kk++) acc += xs[kk] * Wq[kk * 512 + j];
        int h = j >> 6, dd = j & 63;
        g_q[(((size_t)b * HH + h) * 64 + k) * 64 + dd] = __float2bfloat16(acc * 0.125f);
    }
}

// ---------------- K2: KV projection GEMM (bf16 HMMA) ------------------------
// C[131072,1024] = hits_bf16[131072,256] @ Wkvt^T ; tiles 128x128, BK=32, dbuf
#define KSTR2 40
__global__ void __launch_bounds__(256) kv_gemm() {
    __shared__ __nv_bfloat16 As[2 * 128 * KSTR2];
    __shared__ __nv_bfloat16 Bs[2 * 128 * KSTR2];
    int n0 = blockIdx.x * 128;
    int m0 = blockIdx.y * 128;
    int tid = threadIdx.x, lane = tid & 31, warp = tid >> 5;
    int wm = (warp >> 1) * 32, wn = (warp & 1) * 64;
    float acc[2][8][4] = {};

    auto load = [&](int buf, int kt) {
        int k0 = kt * 32;
#pragma unroll
        for (int i = 0; i < 2; i++) {
            int c = tid + 256 * i;
            int row = c >> 2, seg = (c & 3) * 8;
            cpasync16(&As[buf * 128 * KSTR2 + row * KSTR2 + seg],
                      g_hits + (size_t)(m0 + row) * 256 + k0 + seg);
            cpasync16(&Bs[buf * 128 * KSTR2 + row * KSTR2 + seg],
                      g_Wkvt + (size_t)(n0 + row) * 256 + k0 + seg);
        }
        asm volatile("cp.async.commit_group;" ::: "memory");
    };

    load(0, 0);
#pragma unroll
    for (int kt = 0; kt < 8; kt++) {
        if (kt < 7) {
            load((kt + 1) & 1, kt + 1);
            asm volatile("cp.async.wait_group 1;" ::: "memory");
        } else {
            asm volatile("cp.async.wait_group 0;" ::: "memory");
        }
        __syncthreads();
        const __nv_bfloat16* Ab = As + (kt & 1) * 128 * KSTR2;
        const __nv_bfloat16* Bb = Bs + (kt & 1) * 128 * KSTR2;
#pragma unroll
        for (int ks = 0; ks < 2; ks++) {
            uint32_t af[2][4];
#pragma unroll
            for (int mi = 0; mi < 2; mi++)
                ldsm4(af[mi][0], af[mi][1], af[mi][2], af[mi][3],
                      Ab + (wm + mi * 16 + (lane & 15)) * KSTR2 + ks * 16 + (lane >> 4) * 8);
#pragma unroll
            for (int np = 0; np < 4; np++) {
                uint32_t b0, b1, b2, b3;
                int nrow = wn + np * 16 + (lane & 7) + ((lane >> 4) << 3);
                ldsm4(b0, b1, b2, b3, Bb + nrow * KSTR2 + ks * 16 + (lane & 8));
                mma16816(acc[0][2 * np],     af[0], b0, b1);
                mma16816(acc[0][2 * np + 1], af[0], b2, b3);
                mma16816(acc[1][2 * np],     af[1], b0, b1);
                mma16816(acc[1][2 * np + 1], af[1], b2, b3);
            }
        }
        __syncthreads();
    }
    int g = lane >> 2, t4 = lane & 3;
#pragma unroll
    for (int mi = 0; mi < 2; mi++) {
        int row = m0 + wm + mi * 16 + g;
#pragma unroll
        for (int nj = 0; nj < 8; nj++) {
            int col = n0 + wn + nj * 8 + 2 * t4;
            __nv_bfloat162 v0 = __floats2bfloat162_rn(acc[mi][nj][0], acc[mi][nj][1]);
            __nv_bfloat162 v1 = __floats2bfloat162_rn(acc[mi][nj][2], acc[mi][nj][3]);
            *reinterpret_cast<__nv_bfloat162*>(&g_kv[(size_t)row * 1024 + col]) = v0;
            *reinterpret_cast<__nv_bfloat162*>(&g_kv[(size_t)(row + 8) * 1024 + col]) = v1;
        }
    }
}

// ---------------- K3: flash attention, split over N -------------------------
__global__ void __launch_bounds__(128) attn_kernel() {
    __shared__ __nv_bfloat16 Qs[64 * 72];
    __shared__ __nv_bfloat16 Ks[128 * 72];
    __shared__ __nv_bfloat16 Vs[128 * 72];
    int s = blockIdx.x, h = blockIdx.y, b = blockIdx.z;
    int bh = b * HH + h;
    int tid = threadIdx.x, lane = tid & 31, warp = tid >> 5;

#pragma unroll
    for (int i = 0; i < 4; i++) {
        int c = tid + 128 * i;
        int row = c >> 3, seg = (c & 7) * 8;
        *(uint4*)&Qs[row * 72 + seg] =
            *(const uint4*)&g_q[((size_t)bh * 64 + row) * 64 + seg];
    }
    __syncthreads();
    uint32_t qa[4][4];
#pragma unroll
    for (int ks = 0; ks < 4; ks++)
        ldsm4(qa[ks][0], qa[ks][1], qa[ks][2], qa[ks][3],
              Qs + (warp * 16 + (lane & 15)) * 72 + ks * 16 + (lane >> 4) * 8);

    float mrow[2] = {-1e30f, -1e30f}, lrow[2] = {0.f, 0.f};
    float oacc[8][4] = {};
    const __nv_bfloat16* kvb = g_kv + (size_t)b * NN * 1024;

    for (int it = 0; it < 16; it++) {
        int n0 = s * 2048 + it * 128;
#pragma unroll
        for (int i = 0; i < 8; i++) {
            int c = tid + 128 * i;
            int row = c >> 3, seg = (c & 7) * 8;
            const __nv_bfloat16* src = kvb + (size_t)(n0 + row) * 1024 + h * 64 + seg;
            *(uint4*)&Ks[row * 72 + seg] = *(const uint4*)src;
            *(uint4*)&Vs[row * 72 + seg] = *(const uint4*)(src + 512);
        }
        __syncthreads();

        float sacc[16][4] = {};
#pragma unroll
        for (int ks = 0; ks < 4; ks++) {
#pragma unroll
            for (int np = 0; np < 8; np++) {
                uint32_t b0, b1, b2, b3;
                int nrow = np * 16 + (lane & 7) + ((lane >> 4) << 3);
                ldsm4(b0, b1, b2, b3, Ks + nrow * 72 + ks * 16 + (lane & 8));
                mma16816(sacc[2 * np],     qa[ks], b0, b1);
                mma16816(sacc[2 * np + 1], qa[ks], b2, b3);
            }
        }

        // online softmax (rows g and g+8 per thread)
#pragma unroll
        for (int r = 0; r < 2; r++) {
            float mx = -1e30f;
#pragma unroll
            for (int nt = 0; nt < 16; nt++)
                mx = fmaxf(mx, fmaxf(sacc[nt][2 * r], sacc[nt][2 * r + 1]));
            mx = fmaxf(mx, __shfl_xor_sync(0xffffffffu, mx, 1));
            mx = fmaxf(mx, __shfl_xor_sync(0xffffffffu, mx, 2));
            float mnew = fmaxf(mrow[r], mx);
            float sc = __expf(mrow[r] - mnew);
            mrow[r] = mnew;
            float sum = 0.f;
#pragma unroll
            for (int nt = 0; nt < 16; nt++) {
                float p0 = __expf(sacc[nt][2 * r] - mnew);
                float p1 = __expf(sacc[nt][2 * r + 1] - mnew);
                sacc[nt][2 * r] = p0; sacc[nt][2 * r + 1] = p1;
                sum += p0 + p1;
            }
            sum += __shfl_xor_sync(0xffffffffu, sum, 1);
            sum += __shfl_xor_sync(0xffffffffu, sum, 2);
            lrow[r] = lrow[r] * sc + sum;
#pragma unroll
            for (int dt = 0; dt < 8; dt++) { oacc[dt][2 * r] *= sc; oacc[dt][2 * r + 1] *= sc; }
        }

        uint32_t pf[8][4];
#pragma unroll
        for (int k2 = 0; k2 < 8; k2++) {
            pf[k2][0] = packbf(sacc[2 * k2][0],     sacc[2 * k2][1]);
            pf[k2][1] = packbf(sacc[2 * k2][2],     sacc[2 * k2][3]);
            pf[k2][2] = packbf(sacc[2 * k2 + 1][0], sacc[2 * k2 + 1][1]);
            pf[k2][3] = packbf(sacc[2 * k2 + 1][2], sacc[2 * k2 + 1][3]);
        }
#pragma unroll
        for (int k2 = 0; k2 < 8; k2++) {
#pragma unroll
            for (int dp = 0; dp < 4; dp++) {
                uint32_t v0, v1, v2, v3;
                ldsm4t(v0, v1, v2, v3,
                       Vs + (k2 * 16 + (lane & 15)) * 72 + dp * 16 + (lane >> 4) * 8);
                mma16816(oacc[2 * dp],     pf[k2], v0, v1);
                mma16816(oacc[2 * dp + 1], pf[k2], v2, v3);
            }
        }
        __syncthreads();
    }

    // write partials
    int g = lane >> 2, t4 = lane & 3;
    int base = (bh * NSPLIT + s) * 64;
    int r0 = warp * 16 + g;
    if (t4 == 0) {
        g_pm[base + r0] = mrow[0]; g_pm[base + r0 + 8] = mrow[1];
        g_pl[base + r0] = lrow[0]; g_pl[base + r0 + 8] = lrow[1];
    }
#pragma unroll
    for (int dt = 0; dt < 8; dt++) {
        int col = dt * 8 + 2 * t4;
        *(float2*)&g_po[(size_t)(base + r0) * 64 + col]     = make_float2(oacc[dt][0], oacc[dt][1]);
        *(float2*)&g_po[(size_t)(base + r0 + 8) * 64 + col] = make_float2(oacc[dt][2], oacc[dt][3]);
    }
}

// ---------------- K4: combine splits -> att_v -------------------------------
__global__ void combine_splits() {
    int blk = blockIdx.x;              // 0..4095
    int bh = blk >> 6, kslot = blk & 63;
    int d = threadIdx.x;               // 64 threads
    float M = -1e30f;
#pragma unroll
    for (int s = 0; s < NSPLIT; s++) M = fmaxf(M, g_pm[(bh * NSPLIT + s) * 64 + kslot]);
    float L = 0.f, acc = 0.f;
#pragma unroll
    for (int s = 0; s < NSPLIT; s++) {
        int idx = (bh * NSPLIT + s) * 64 + kslot;
        float w = __expf(g_pm[idx] - M);
        L   += g_pl[idx] * w;
        acc += g_po[(size_t)idx * 64 + d] * w;
    }
    int b = bh >> 3, h = bh & 7;
    g_attv[((size_t)(b * KSLOT + kslot)) * 512 + h * 64 + d] = acc / L;
}

// ---------------- K5: MLP + residual + LN2 ----------------------------------
__global__ void __launch_bounds__(256) mlp_ln2(const float* __restrict__ slots,
                                               const float* __restrict__ W1,
                                               const float* __restrict__ b1,
                                               const float* __restrict__ W2,
                                               const float* __restrict__ b2,
                                               const float* __restrict__ g2,
                                               const float* __restrict__ be2,
                                               float* __restrict__ out) {
    __shared__ float av[8][512];
    __shared__ float hid[8][512];
    __shared__ float red[256];
    int t = threadIdx.x;
    int r0 = blockIdx.x * 8;
#pragma unroll
    for (int r = 0; r < 8; r++) {
        av[r][t]       = g_attv[(size_t)(r0 + r) * 512 + t];
        av[r][t + 256] = g_attv[(size_t)(r0 + r) * 512 + t + 256];
    }
    __syncthreads();
    float a0[8], a1[8];
    float bb0 = b1[t], bb1 = b1[t + 256];
#pragma unroll
    for (int r = 0; r < 8; r++) { a0[r] = bb0; a1[r] = bb1; }
    for (int kk = 0; kk < 512; kk++) {
        float w0 = W1[kk * 512 + t];
        float w1 = W1[kk * 512 + t + 256];
#pragma unroll
        for (int r = 0; r < 8; r++) {
            float x = av[r][kk];
            a0[r] += x * w0; a1[r] += x * w1;
        }
    }
#pragma unroll
    for (int r = 0; r < 8; r++) {
        hid[r][t] = fmaxf(a0[r], 0.f);
        hid[r][t + 256] = fmaxf(a1[r], 0.f);
    }
    __syncthreads();
    float o[8];
    float c0 = b2[t];
#pragma unroll
    for (int r = 0; r < 8; r++) o[r] = c0;
    for (int kk = 0; kk < 512; kk++) {
        float w = W2[kk * 256 + t];
#pragma unroll
        for (int r = 0; r < 8; r++) o[r] += hid[r][kk] * w;
    }
    float gg = g2[t], bbn = be2[t];
    for (int r = 0; r < 8; r++) {
        float x = slots[(size_t)(r0 + r) * 256 + t] + o[r];
        red[t] = x; __syncthreads();
        for (int off = 128; off; off >>= 1) { if (t < off) red[t] += red[t + off]; __syncthreads(); }
        float mean = red[0] * (1.f / 256.f); __syncthreads();
        float d = x - mean;
        red[t] = d * d; __syncthreads();
        for (int off = 128; off; off >>= 1) { if (t < off) red[t] += red[t + off]; __syncthreads(); }
        float var = red[0] * (1.f / 256.f); __syncthreads();
        out[(size_t)(r0 + r) * 256 + t] = d * rsqrtf(var + 1e-5f) * gg + bbn;
    }
}

// ---------------- launch -----------------------------------------------------
extern "C" void kernel_launch(void* const* d_in, const int* in_sizes, int n_in,
                              void* d_out, int out_size) {
    const float* slots = (const float*)d_in[0];
    const float* hits  = (const float*)d_in[1];
    const float* ln1g  = (const float*)d_in[2];
    const float* ln1b  = (const float*)d_in[3];
    const float* Wq    = (const float*)d_in[4];
    const float* Wk    = (const float*)d_in[5];
    const float* Wv    = (const float*)d_in[6];
    const float* W1    = (const float*)d_in[7];
    const float* b1    = (const float*)d_in[8];
    const float* W2    = (const float*)d_in[9];
    const float* b2    = (const float*)d_in[10];
    const float* ln2g  = (const float*)d_in[11];
    const float* ln2b  = (const float*)d_in[12];
    float* out = (float*)d_out;

    int nvec = (BB * NN * DQ) / 4;
    cvt_hits<<<8192, 256>>>((const float4*)hits, nvec);
    prep_w<<<1024, 256>>>(Wk, Wv);
    ln1_q<<<512, 256>>>(slots, ln1g, ln1b, Wq);
    kv_gemm<<<dim3(8, 1024), 256>>>();
    attn_kernel<<<dim3(NSPLIT, HH, BB), 128>>>();
    combine_splits<<<4096, 64>>>();
    mlp_ln2<<<64, 256>>>(slots, W1, b1, W2, b2, ln2g, ln2b, out);
}

// round 2
// speedup vs baseline: 1.3240x; 1.3240x over previous
#include <cuda_runtime.h>
#include <cuda_bf16.h>
#include <cstdint>

#define BB 8
#define HH 8
#define NN 16384
#define KSLOT 64
#define DQ 256
#define DMLP 512
#define NSPLIT 16          // splits per batch (16 CTAs per b, 128 total)
#define CH 128             // N rows per chunk
#define NCHUNK 8           // chunks per CTA per head (1024 rows / CTA)

// ---------------- scratch -----------------------------------------------------
__device__ __nv_bfloat16 g_hits[(size_t)BB * NN * DQ];          // 67 MB
__device__ __nv_bfloat16 g_Wkvt[1024 * 256];                    // [out col][k]
__device__ __nv_bfloat16 g_q[(size_t)BB * HH * 64 * 64];        // [b][h][k][d] *0.125
__device__ float g_pm[BB * HH * NSPLIT * 64];
__device__ float g_pl[BB * HH * NSPLIT * 64];
__device__ float g_po[(size_t)BB * HH * NSPLIT * 64 * 64];
__device__ float g_attv[(size_t)BB * KSLOT * 512];

// ---------------- PTX helpers --------------------------------------------------
__device__ __forceinline__ uint32_t smaddr(const void* p) {
    return (uint32_t)__cvta_generic_to_shared(p);
}
__device__ __forceinline__ void ldsm4(uint32_t& r0, uint32_t& r1, uint32_t& r2, uint32_t& r3,
                                      const void* p) {
    uint32_t a = smaddr(p);
    asm volatile("ldmatrix.sync.aligned.m8n8.x4.shared.b16 {%0,%1,%2,%3},[%4];"
                 : "=r"(r0), "=r"(r1), "=r"(r2), "=r"(r3) : "r"(a));
}
__device__ __forceinline__ void ldsm4t(uint32_t& r0, uint32_t& r1, uint32_t& r2, uint32_t& r3,
                                       const void* p) {
    uint32_t a = smaddr(p);
    asm volatile("ldmatrix.sync.aligned.m8n8.x4.trans.shared.b16 {%0,%1,%2,%3},[%4];"
                 : "=r"(r0), "=r"(r1), "=r"(r2), "=r"(r3) : "r"(a));
}
__device__ __forceinline__ void mma16816(float* c, const uint32_t* a, uint32_t b0, uint32_t b1) {
    asm volatile("mma.sync.aligned.m16n8k16.row.col.f32.bf16.bf16.f32 "
                 "{%0,%1,%2,%3},{%4,%5,%6,%7},{%8,%9},{%0,%1,%2,%3};"
                 : "+f"(c[0]), "+f"(c[1]), "+f"(c[2]), "+f"(c[3])
                 : "r"(a[0]), "r"(a[1]), "r"(a[2]), "r"(a[3]), "r"(b0), "r"(b1));
}
__device__ __forceinline__ void cpasync16(void* dst, const void* src) {
    uint32_t d = smaddr(dst);
    asm volatile("cp.async.ca.shared.global [%0],[%1],16;" :: "r"(d), "l"(src) : "memory");
}
__device__ __forceinline__ void cpcommit() { asm volatile("cp.async.commit_group;" ::: "memory"); }
__device__ __forceinline__ uint32_t packbf(float a, float b) {
    __nv_bfloat162 t = __floats2bfloat162_rn(a, b);
    return *reinterpret_cast<uint32_t*>(&t);
}

// ---------------- K0a: hits fp32 -> bf16 --------------------------------------
__global__ void cvt_hits(const float4* __restrict__ in, int nvec) {
    __nv_bfloat162* out = reinterpret_cast<__nv_bfloat162*>(g_hits);
    for (int i = blockIdx.x * blockDim.x + threadIdx.x; i < nvec; i += gridDim.x * blockDim.x) {
        float4 v = in[i];
        out[2 * i]     = __floats2bfloat162_rn(v.x, v.y);
        out[2 * i + 1] = __floats2bfloat162_rn(v.z, v.w);
    }
}

// ---------------- K0b: [Wk|Wv] transposed -> bf16 ------------------------------
__global__ void prep_w(const float* __restrict__ Wk, const float* __restrict__ Wv) {
    int i = blockIdx.x * blockDim.x + threadIdx.x;
    int j = i >> 8, kk = i & 255;
    float v = (j < 512) ? Wk[kk * 512 + j] : Wv[kk * 512 + (j - 512)];
    g_Wkvt[i] = __float2bfloat16(v);
}

// ---------------- K1: LN1 + Q projection ---------------------------------------
__global__ void __launch_bounds__(256) ln1_q(const float* __restrict__ slots,
                                             const float* __restrict__ g1,
                                             const float* __restrict__ be1,
                                             const float* __restrict__ Wq) {
    __shared__ float xs[256];
    __shared__ float red[256];
    int row = blockIdx.x, t = threadIdx.x;
    int b = row >> 6, k = row & 63;
    float x = slots[(size_t)row * 256 + t];
    red[t] = x; __syncthreads();
    for (int off = 128; off; off >>= 1) { if (t < off) red[t] += red[t + off]; __syncthreads(); }
    float mean = red[0] * (1.f / 256.f);
    __syncthreads();
    float d = x - mean;
    red[t] = d * d; __syncthreads();
    for (int off = 128; off; off >>= 1) { if (t < off) red[t] += red[t + off]; __syncthreads(); }
    float var = red[0] * (1.f / 256.f);
    float xn = d * rsqrtf(var + 1e-5f) * g1[t] + be1[t];
    __syncthreads();
    xs[t] = xn;
    __syncthreads();
#pragma unroll
    for (int jj = 0; jj < 2; jj++) {
        int j = t + jj * 256;
        float acc = 0.f;
#pragma unroll 8
        for (int kk = 0; kk < 256; kk++) acc += xs[kk] * Wq[kk * 512 + j];
        int h = j >> 6, dd = j & 63;
        g_q[(((size_t)b * HH + h) * 64 + k) * 64 + dd] = __float2bfloat16(acc * 0.125f);
    }
}

// ---------------- fused KV-projection + flash attention ------------------------
// grid: (NSPLIT, BB), 256 threads. smem ~199KB, 1 CTA/SM.
#define HSTR 264   // hits / weight tile row stride (elems)
#define KVSTR 72   // K/V tile row stride

struct FusedSmem {
    __nv_bfloat16 Qs[64 * KVSTR];        // 9216 B
    __nv_bfloat16 Hs[128 * HSTR];        // 67584 B
    __nv_bfloat16 Wks[64 * HSTR];        // 33792 B
    __nv_bfloat16 Wvs[64 * HSTR];        // 33792 B
    __nv_bfloat16 Ks[128 * KVSTR];       // 18432 B
    __nv_bfloat16 Vs[128 * KVSTR];       // 18432 B
    float Ocomb[64 * 64];                // 16384 B
    float mx_xch[2][64];
    float sm_xch[2][64];
};

__global__ void __launch_bounds__(256, 1) fused_attn() {
    extern __shared__ char smraw[];
    FusedSmem& sm = *reinterpret_cast<FusedSmem*>(smraw);

    const int s = blockIdx.x, b = blockIdx.y;
    const int tid = threadIdx.x, lane = tid & 31, warp = tid >> 5;
    const int wm = (warp >> 1) * 32, wn = (warp & 1) * 32;   // projection tiling
    const int p = warp & 3, hf = warp >> 2;                   // attention tiling
    const int g = lane >> 2, t4 = lane & 3;

    const size_t cta_row0 = (size_t)b * NN + (size_t)s * (NN / NSPLIT);

    // per-chunk hits loader: two halves (two commit groups)
    auto load_hits = [&](int c) {
        size_t r0 = cta_row0 + (size_t)c * CH;
#pragma unroll
        for (int hl = 0; hl < 2; hl++) {
#pragma unroll
            for (int i = 0; i < 4; i++) {
                int idx = tid + 256 * i;               // 0..1023
                int row = idx >> 3, seg = (idx & 7) * 16 + hl * 8; // wrong split? fix below
                (void)row; (void)seg;
            }
            // proper: 2048 16B vectors per half, 8 per thread
#pragma unroll
            for (int i = 0; i < 8; i++) {
                int idx = tid + 256 * i;               // 0..2047
                int row = idx >> 4, seg = (idx & 15) * 8;
                cpasync16(&sm.Hs[row * HSTR + hl * 128 + seg],
                          g_hits + (r0 + row) * 256 + hl * 128 + seg);
            }
            cpcommit();
        }
    };

    for (int h = 0; h < HH; h++) {
        const int bh = b * HH + h;
        // ---- load Wk_h / Wv_h tiles (one commit group) ----
#pragma unroll
        for (int i = 0; i < 4; i++) {
            int idx = tid + 256 * i;                   // 0..1023
            int row = idx >> 4, seg = (idx & 15) * 8;
            cpasync16(&sm.Wks[row * HSTR + seg], g_Wkvt + (size_t)(h * 64 + row) * 256 + seg);
        }
#pragma unroll
        for (int i = 0; i < 4; i++) {
            int idx = tid + 256 * i;
            int row = idx >> 4, seg = (idx & 15) * 8;
            cpasync16(&sm.Wvs[row * HSTR + seg], g_Wkvt + (size_t)(512 + h * 64 + row) * 256 + seg);
        }
        cpcommit();
        // ---- stage Q ----
#pragma unroll
        for (int i = 0; i < 2; i++) {
            int idx = tid + 256 * i;                   // 0..511
            int row = idx >> 3, seg = (idx & 7) * 8;
            *(uint4*)&sm.Qs[row * KVSTR + seg] =
                *(const uint4*)&g_q[((size_t)bh * 64 + row) * 64 + seg];
        }
        // ---- prefetch chunk 0 ----
        load_hits(0);
        __syncthreads();
        uint32_t qa[4][4];
#pragma unroll
        for (int ks = 0; ks < 4; ks++)
            ldsm4(qa[ks][0], qa[ks][1], qa[ks][2], qa[ks][3],
                  sm.Qs + (p * 16 + (lane & 15)) * KVSTR + ks * 16 + (lane >> 4) * 8);

        float mrow[2] = {-1e30f, -1e30f}, lrow[2] = {0.f, 0.f};
        float oacc[8][4] = {};

        for (int c = 0; c < NCHUNK; c++) {
            // ================= projection: K,V [128x64] =================
            float kacc[2][4][4] = {}, vacc[2][4][4] = {};
#pragma unroll
            for (int hl = 0; hl < 2; hl++) {
                if (hl == 0) asm volatile("cp.async.wait_group 1;" ::: "memory");
                else         asm volatile("cp.async.wait_group 0;" ::: "memory");
                __syncthreads();
#pragma unroll
                for (int k8 = 0; k8 < 8; k8++) {
                    int ks = hl * 8 + k8;
                    uint32_t af[2][4];
#pragma unroll
                    for (int mi = 0; mi < 2; mi++)
                        ldsm4(af[mi][0], af[mi][1], af[mi][2], af[mi][3],
                              sm.Hs + (wm + mi * 16 + (lane & 15)) * HSTR + ks * 16 + (lane >> 4) * 8);
#pragma unroll
                    for (int nb = 0; nb < 2; nb++) {
                        int nrow = wn + nb * 16 + (lane & 7) + ((lane >> 4) << 3);
                        uint32_t b0, b1, b2, b3;
                        ldsm4(b0, b1, b2, b3, sm.Wks + nrow * HSTR + ks * 16 + (lane & 8));
                        mma16816(kacc[0][2 * nb],     af[0], b0, b1);
                        mma16816(kacc[0][2 * nb + 1], af[0], b2, b3);
                        mma16816(kacc[1][2 * nb],     af[1], b0, b1);
                        mma16816(kacc[1][2 * nb + 1], af[1], b2, b3);
                        uint32_t c0, c1, c2, c3;
                        ldsm4(c0, c1, c2, c3, sm.Wvs + nrow * HSTR + ks * 16 + (lane & 8));
                        mma16816(vacc[0][2 * nb],     af[0], c0, c1);
                        mma16816(vacc[0][2 * nb + 1], af[0], c2, c3);
                        mma16816(vacc[1][2 * nb],     af[1], c0, c1);
                        mma16816(vacc[1][2 * nb + 1], af[1], c2, c3);
                    }
                }
            }
            __syncthreads();   // Hs consumed; prev attention done with Ks/Vs
            // epilogue -> smem bf16 K/V tiles
#pragma unroll
            for (int mi = 0; mi < 2; mi++) {
                int row = wm + mi * 16 + g;
#pragma unroll
                for (int nj = 0; nj < 4; nj++) {
                    int col = wn + nj * 8 + 2 * t4;
                    *(uint32_t*)&sm.Ks[row * KVSTR + col]       = packbf(kacc[mi][nj][0], kacc[mi][nj][1]);
                    *(uint32_t*)&sm.Ks[(row + 8) * KVSTR + col] = packbf(kacc[mi][nj][2], kacc[mi][nj][3]);
                    *(uint32_t*)&sm.Vs[row * KVSTR + col]       = packbf(vacc[mi][nj][0], vacc[mi][nj][1]);
                    *(uint32_t*)&sm.Vs[(row + 8) * KVSTR + col] = packbf(vacc[mi][nj][2], vacc[mi][nj][3]);
                }
            }
            if (c + 1 < NCHUNK) load_hits(c + 1);   // overlap with attention
            __syncthreads();

            // ================= attention: QK^T, softmax, PV =================
            float sacc[8][4] = {};
#pragma unroll
            for (int ks = 0; ks < 4; ks++) {
#pragma unroll
                for (int np = 0; np < 4; np++) {
                    int nrow = hf * 64 + np * 16 + (lane & 7) + ((lane >> 4) << 3);
                    uint32_t b0, b1, b2, b3;
                    ldsm4(b0, b1, b2, b3, sm.Ks + nrow * KVSTR + ks * 16 + (lane & 8));
                    mma16816(sacc[2 * np],     qa[ks], b0, b1);
                    mma16816(sacc[2 * np + 1], qa[ks], b2, b3);
                }
            }
            // local row-max over this n-half
            float mxv[2];
#pragma unroll
            for (int r = 0; r < 2; r++) {
                float mx = -1e30f;
#pragma unroll
                for (int nt = 0; nt < 8; nt++)
                    mx = fmaxf(mx, fmaxf(sacc[nt][2 * r], sacc[nt][2 * r + 1]));
                mx = fmaxf(mx, __shfl_xor_sync(0xffffffffu, mx, 1));
                mx = fmaxf(mx, __shfl_xor_sync(0xffffffffu, mx, 2));
                mxv[r] = mx;
            }
            if (t4 == 0) {
                sm.mx_xch[hf][p * 16 + g]     = mxv[0];
                sm.mx_xch[hf][p * 16 + g + 8] = mxv[1];
            }
            __syncthreads();
            float sc[2];
#pragma unroll
            for (int r = 0; r < 2; r++) {
                int row = p * 16 + g + r * 8;
                float mAll = fmaxf(sm.mx_xch[0][row], sm.mx_xch[1][row]);
                float mnew = fmaxf(mrow[r], mAll);
                sc[r] = __expf(mrow[r] - mnew);
                mrow[r] = mnew;
                float sum = 0.f;
#pragma unroll
                for (int nt = 0; nt < 8; nt++) {
                    float p0 = __expf(sacc[nt][2 * r] - mnew);
                    float p1 = __expf(sacc[nt][2 * r + 1] - mnew);
                    sacc[nt][2 * r] = p0; sacc[nt][2 * r + 1] = p1;
                    sum += p0 + p1;
                }
                sum += __shfl_xor_sync(0xffffffffu, sum, 1);
                sum += __shfl_xor_sync(0xffffffffu, sum, 2);
                if (t4 == 0) sm.sm_xch[hf][row] = sum;
            }
            __syncthreads();
#pragma unroll
            for (int r = 0; r < 2; r++) {
                int row = p * 16 + g + r * 8;
                lrow[r] = lrow[r] * sc[r] + sm.sm_xch[0][row] + sm.sm_xch[1][row];
#pragma unroll
                for (int dt = 0; dt < 8; dt++) {
                    oacc[dt][2 * r] *= sc[r]; oacc[dt][2 * r + 1] *= sc[r];
                }
            }
            // P@V over this n-half
            uint32_t pf[4][4];
#pragma unroll
            for (int k2 = 0; k2 < 4; k2++) {
                pf[k2][0] = packbf(sacc[2 * k2][0],     sacc[2 * k2][1]);
                pf[k2][1] = packbf(sacc[2 * k2][2],     sacc[2 * k2][3]);
                pf[k2][2] = packbf(sacc[2 * k2 + 1][0], sacc[2 * k2 + 1][1]);
                pf[k2][3] = packbf(sacc[2 * k2 + 1][2], sacc[2 * k2 + 1][3]);
            }
#pragma unroll
            for (int k2 = 0; k2 < 4; k2++) {
#pragma unroll
                for (int dp = 0; dp < 4; dp++) {
                    uint32_t v0, v1, v2, v3;
                    ldsm4t(v0, v1, v2, v3,
                           sm.Vs + (hf * 64 + k2 * 16 + (lane & 15)) * KVSTR + dp * 16 + (lane >> 4) * 8);
                    mma16816(oacc[2 * dp],     pf[k2], v0, v1);
                    mma16816(oacc[2 * dp + 1], pf[k2], v2, v3);
                }
            }
        } // chunks

        // ---- head epilogue: combine halves, write partials ----
        const int base = (bh * NSPLIT + s) * 64;
        const int r0 = p * 16 + g;
        __syncthreads();
        if (hf == 0) {
#pragma unroll
            for (int dt = 0; dt < 8; dt++) {
                int col = dt * 8 + 2 * t4;
                *(float2*)&sm.Ocomb[r0 * 64 + col]       = make_float2(oacc[dt][0], oacc[dt][1]);
                *(float2*)&sm.Ocomb[(r0 + 8) * 64 + col] = make_float2(oacc[dt][2], oacc[dt][3]);
            }
            if (t4 == 0) {
                g_pm[base + r0] = mrow[0]; g_pm[base + r0 + 8] = mrow[1];
                g_pl[base + r0] = lrow[0]; g_pl[base + r0 + 8] = lrow[1];
            }
        }
        __syncthreads();
        if (hf == 1) {
#pragma unroll
            for (int dt = 0; dt < 8; dt++) {
                int col = dt * 8 + 2 * t4;
                float2 a = *(float2*)&sm.Ocomb[r0 * 64 + col];
                float2 bb = *(float2*)&sm.Ocomb[(r0 + 8) * 64 + col];
                *(float2*)&g_po[(size_t)(base + r0) * 64 + col] =
                    make_float2(a.x + oacc[dt][0], a.y + oacc[dt][1]);
                *(float2*)&g_po[(size_t)(base + r0 + 8) * 64 + col] =
                    make_float2(bb.x + oacc[dt][2], bb.y + oacc[dt][3]);
            }
        }
        __syncthreads();
    } // heads
}

// ---------------- combine splits -> att_v ---------------------------------------
__global__ void combine_splits() {
    int blk = blockIdx.x;              // 0..4095
    int bh = blk >> 6, kslot = blk & 63;
    int d = threadIdx.x;               // 64 threads
    float M = -1e30f;
#pragma unroll
    for (int s = 0; s < NSPLIT; s++) M = fmaxf(M, g_pm[(bh * NSPLIT + s) * 64 + kslot]);
    float L = 0.f, acc = 0.f;
#pragma unroll
    for (int s = 0; s < NSPLIT; s++) {
        int idx = (bh * NSPLIT + s) * 64 + kslot;
        float w = __expf(g_pm[idx] - M);
        L   += g_pl[idx] * w;
        acc += g_po[(size_t)idx * 64 + d] * w;
    }
    int b = bh >> 3, h = bh & 7;
    g_attv[((size_t)(b * KSLOT + kslot)) * 512 + h * 64 + d] = acc / L;
}

// ---------------- MLP + residual + LN2 ------------------------------------------
#define MLPR 4
__global__ void __launch_bounds__(256) mlp_ln2(const float* __restrict__ slots,
                                               const float* __restrict__ W1,
                                               const float* __restrict__ b1,
                                               const float* __restrict__ W2,
                                               const float* __restrict__ b2,
                                               const float* __restrict__ g2,
                                               const float* __restrict__ be2,
                                               float* __restrict__ out) {
    __shared__ float av[MLPR][512];
    __shared__ float hid[MLPR][512];
    __shared__ float red[256];
    int t = threadIdx.x;
    int r0 = blockIdx.x * MLPR;
#pragma unroll
    for (int r = 0; r < MLPR; r++) {
        av[r][t]       = g_attv[(size_t)(r0 + r) * 512 + t];
        av[r][t + 256] = g_attv[(size_t)(r0 + r) * 512 + t + 256];
    }
    __syncthreads();
    float a0[MLPR], a1[MLPR];
    float bb0 = b1[t], bb1 = b1[t + 256];
#pragma unroll
    for (int r = 0; r < MLPR; r++) { a0[r] = bb0; a1[r] = bb1; }
    for (int kk = 0; kk < 512; kk++) {
        float w0 = W1[kk * 512 + t];
        float w1 = W1[kk * 512 + t + 256];
#pragma unroll
        for (int r = 0; r < MLPR; r++) {
            float x = av[r][kk];
            a0[r] += x * w0; a1[r] += x * w1;
        }
    }
#pragma unroll
    for (int r = 0; r < MLPR; r++) {
        hid[r][t] = fmaxf(a0[r], 0.f);
        hid[r][t + 256] = fmaxf(a1[r], 0.f);
    }
    __syncthreads();
    float o[MLPR];
    float c0 = b2[t];
#pragma unroll
    for (int r = 0; r < MLPR; r++) o[r] = c0;
    for (int kk = 0; kk < 512; kk++) {
        float w = W2[kk * 256 + t];
#pragma unroll
        for (int r = 0; r < MLPR; r++) o[r] += hid[r][kk] * w;
    }
    float gg = g2[t], bbn = be2[t];
    for (int r = 0; r < MLPR; r++) {
        float x = slots[(size_t)(r0 + r) * 256 + t] + o[r];
        red[t] = x; __syncthreads();
        for (int off = 128; off; off >>= 1) { if (t < off) red[t] += red[t + off]; __syncthreads(); }
        float mean = red[0] * (1.f / 256.f); __syncthreads();
        float d = x - mean;
        red[t] = d * d; __syncthreads();
        for (int off = 128; off; off >>= 1) { if (t < off) red[t] += red[t + off]; __syncthreads(); }
        float var = red[0] * (1.f / 256.f); __syncthreads();
        out[(size_t)(r0 + r) * 256 + t] = d * rsqrtf(var + 1e-5f) * gg + bbn;
    }
}

// ---------------- launch ----------------------------------------------------------
extern "C" void kernel_launch(void* const* d_in, const int* in_sizes, int n_in,
                              void* d_out, int out_size) {
    const float* slots = (const float*)d_in[0];
    const float* hits  = (const float*)d_in[1];
    const float* ln1g  = (const float*)d_in[2];
    const float* ln1b  = (const float*)d_in[3];
    const float* Wq    = (const float*)d_in[4];
    const float* Wk    = (const float*)d_in[5];
    const float* Wv    = (const float*)d_in[6];
    const float* W1    = (const float*)d_in[7];
    const float* b1    = (const float*)d_in[8];
    const float* W2    = (const float*)d_in[9];
    const float* b2    = (const float*)d_in[10];
    const float* ln2g  = (const float*)d_in[11];
    const float* ln2b  = (const float*)d_in[12];
    float* out = (float*)d_out;

    cudaFuncSetAttribute(fused_attn, cudaFuncAttributeMaxDynamicSharedMemorySize,
                         (int)sizeof(FusedSmem));

    int nvec = (BB * NN * DQ) / 4;
    cvt_hits<<<8192, 256>>>((const float4*)hits, nvec);
    prep_w<<<1024, 256>>>(Wk, Wv);
    ln1_q<<<512, 256>>>(slots, ln1g, ln1b, Wq);
    fused_attn<<<dim3(NSPLIT, BB), 256, sizeof(FusedSmem)>>>();
    combine_splits<<<4096, 64>>>();
    mlp_ln2<<<BB * KSLOT / MLPR, 256>>>(slots, W1, b1, W2, b2, ln2g, ln2b, out);
}